// round 15
// baseline (speedup 1.0000x reference)
#include <cuda_runtime.h>
#include <cuda_fp16.h>
#include <cstdint>
#include <math.h>

// Problem constants
#define SS 128
#define QQ 64
#define PP 64
#define DD 256
#define NROW (SS*QQ)
#define NE   (SS*PP)
#define INV_TEMP (1.0f/0.07f)
#define LAM 0.1f
#define NCHUNK 1088     // 17 seg * 64 bm
#define GRIDN 296       // 2 CTAs/SM * 148 SMs (all co-resident)

// -------- scratch (device globals) --------
__device__ uint8_t g_q8[NROW*DD];     // normalized questions, row-major e4m3
__device__ uint8_t g_s8[NE*DD];       // normalized sentences,  row-major e4m3
__device__ uint8_t g_st8[SS*DD];      // normalized section titles, row-major e4m3
__device__ float g_pos[SS*QQ*PP];
__device__ float g_Epart[64*NROW];    // [bn][row], each slot written once
__device__ float g_den_part[64*SS];   // [bm][s]
__device__ float g_num_part[SS];
__device__ float g_final_part[SS];
__device__ unsigned g_ticket;
__device__ unsigned g_work;
__device__ unsigned g_bcnt;           // barrier count (self-resetting)
__device__ unsigned g_bgen;           // barrier generation (monotonic)

// ================= helpers =================
__device__ __forceinline__ uint32_t smem_u32(const void* p) {
    uint32_t a;
    asm("{ .reg .u64 t; cvta.to.shared.u64 t, %1; cvt.u32.u64 %0, t; }" : "=r"(a) : "l"(p));
    return a;
}
#define SW128(o) ((o) ^ (((o) >> 3) & 0x70))

__device__ __forceinline__ void cp16(uint32_t dst, const void* src) {
    asm volatile("cp.async.cg.shared.global [%0], [%1], 16;" :: "r"(dst), "l"(src) : "memory");
}
#define CP_COMMIT() asm volatile("cp.async.commit_group;" ::: "memory")
#define CP_WAIT(n)  asm volatile("cp.async.wait_group %0;" :: "n"(n) : "memory")

__device__ __forceinline__ void ldsm4(uint32_t* r, uint32_t addr) {
    asm volatile("ldmatrix.sync.aligned.m8n8.x4.shared.b16 {%0,%1,%2,%3}, [%4];"
        : "=r"(r[0]), "=r"(r[1]), "=r"(r[2]), "=r"(r[3]) : "r"(addr));
}
// fp8 e4m3 x e4m3 -> f16 accumulator (2 b32 regs = 4 halves)
__device__ __forceinline__ void mma16832h(uint32_t* c, const uint32_t* a, const uint32_t* b) {
    asm volatile(
        "mma.sync.aligned.m16n8k32.row.col.f16.e4m3.e4m3.f16 "
        "{%0,%1}, {%2,%3,%4,%5}, {%6,%7}, {%0,%1};"
        : "+r"(c[0]), "+r"(c[1])
        : "r"(a[0]), "r"(a[1]), "r"(a[2]), "r"(a[3]), "r"(b[0]), "r"(b[1]));
}
__device__ __forceinline__ uint16_t f2e4m3x2(float hi, float lo) {
    uint16_t r;
    asm("cvt.rn.satfinite.e4m3x2.f32 %0, %1, %2;" : "=h"(r) : "f"(hi), "f"(lo));
    return r;
}

// ================= normalize -> fp8 (one warp per row; proven) =========
__global__ void __launch_bounds__(256) norm_kernel(const float* __restrict__ q_in,
                                                   const float* __restrict__ s_in,
                                                   const float* __restrict__ st_in) {
    if (blockIdx.x == 0 && threadIdx.x == 0) { g_ticket = 0; g_work = 0; }
    int warp = threadIdx.x >> 5, lane = threadIdx.x & 31;
    int row = blockIdx.x * 8 + warp;        // 2064 blocks * 8 rows = 16512 rows
    const float* src; uint8_t* dst; int col;
    if (row < NROW)        { col = row;          src = q_in  + (size_t)col * DD; dst = g_q8;  }
    else if (row < 2*NROW) { col = row - NROW;   src = s_in  + (size_t)col * DD; dst = g_s8;  }
    else                   { col = row - 2*NROW; src = st_in + (size_t)col * DD; dst = g_st8; }

    float4 v0 = ((const float4*)src)[lane*2];
    float4 v1 = ((const float4*)src)[lane*2 + 1];
    float ss = v0.x*v0.x + v0.y*v0.y + v0.z*v0.z + v0.w*v0.w
             + v1.x*v1.x + v1.y*v1.y + v1.z*v1.z + v1.w*v1.w;
    #pragma unroll
    for (int o = 16; o > 0; o >>= 1) ss += __shfl_xor_sync(0xffffffffu, ss, o);
    float sc = 1.0f / fmaxf(sqrtf(ss), 1e-12f);
    uint32_t lo = (uint32_t)f2e4m3x2(v0.y*sc, v0.x*sc)
                | ((uint32_t)f2e4m3x2(v0.w*sc, v0.z*sc) << 16);
    uint32_t hi = (uint32_t)f2e4m3x2(v1.y*sc, v1.x*sc)
                | ((uint32_t)f2e4m3x2(v1.w*sc, v1.z*sc) << 16);
    *(uint2*)(dst + (size_t)col*DD + lane*8) = make_uint2(lo, hi);
}

// ================= persistent GEMM + loss (work-stealing) =================
// 296 persistent CTAs pull chunks (bm, seg) from g_work. Chunk body = R11.
// After drain: grid barrier, then CTAs 0..127 compute per-section loss +
// ticketed final reduce. smem: A 2x16KB @0; B 4x16KB @32768; scratch @98304.
#define SMEM_GEMM 101376

__device__ __forceinline__ void fill_stage(uint32_t su, const uint8_t* bbase,
                                           int stagebuf, int tid) {
    uint32_t d = su + 32768 + stagebuf * 16384;
    #pragma unroll
    for (int i = 0; i < 4; i++) {
        int idx = i*256 + tid;
        int row = idx >> 3, c16 = (idx & 7) * 16;
        cp16(d + SW128(row*128 + c16), bbase + (size_t)row*256 + c16);
    }
}

// Pipelined MMA over one (128x128 tile) x (K=128 chunk): fragment double-buffer.
__device__ __forceinline__ void mma_chunk(uint32_t (&acc)[2][8][2], uint32_t as, uint32_t bs,
                                          uint32_t laneA, uint32_t laneB) {
    uint32_t a[2][2][4], b[2][4][4];
    {
        const uint32_t a0 = as + laneA, b0 = bs + laneB;
        ldsm4(a[0][0], a0);
        ldsm4(a[0][1], a0 + 2048);
        #pragma unroll
        for (int np = 0; np < 4; np++) ldsm4(b[0][np], b0 + np*2048);
    }
    #pragma unroll
    for (int kk = 0; kk < 4; kk++) {
        const int cur = kk & 1, nxt = cur ^ 1;
        if (kk < 3) {
            const uint32_t x = (uint32_t)(kk + 1) * 32u;
            const uint32_t a0 = as + (laneA ^ x), b0 = bs + (laneB ^ x);
            ldsm4(a[nxt][0], a0);
            ldsm4(a[nxt][1], a0 + 2048);
            #pragma unroll
            for (int np = 0; np < 4; np++) ldsm4(b[nxt][np], b0 + np*2048);
        }
        #pragma unroll
        for (int mt = 0; mt < 2; mt++)
            #pragma unroll
            for (int nt = 0; nt < 8; nt++)
                mma16832h(acc[mt][nt], a[cur][mt], b[cur][nt >> 1] + (nt & 1)*2);
    }
}

__global__ void __launch_bounds__(256, 2) gemm_kernel(float* out) {
    extern __shared__ char smem[];
    const uint32_t su = smem_u32(smem);
    float* fs = (float*)(smem + 98304);
    const int tid = threadIdx.x;
    const int lane = tid & 31, wid = tid >> 5;
    const int wm = wid >> 1, wn = wid & 1;

    // pre-swizzled lane bases (XOR trick: kk*32 toggles bits 5-6 w/o carry)
    const int arow = wm*32 + (lane & 15);
    const int aoff = (lane >> 4) * 16;
    const uint32_t laneA = (uint32_t)(arow*128) + (uint32_t)(aoff ^ ((arow & 7) << 4));
    const int brow = wn*64 + (lane & 7) + ((lane >> 4) & 1) * 8;
    const int boff = ((lane >> 3) & 1) * 16;
    const uint32_t laneB = (uint32_t)(brow*128) + (uint32_t)(boff ^ ((brow & 7) << 4));

    __shared__ unsigned sh_w;
    uint32_t acc[2][8][2];

    // ================= phase 1: work-stealing GEMM chunks =================
    for (;;) {
        if (tid == 0) sh_w = atomicAdd(&g_work, 1u);
        __syncthreads();                       // broadcast + smem reuse guard
        const unsigned w = sh_w;
        if (w >= NCHUNK) break;
        const int seg = (int)(w >> 6);         // 0..16 (seg-major: B tile L2 reuse)
        const int bm  = (int)(w & 63u);

        // ---- A load: 32KB (2 K-chunks), folds into first commit group ----
        {
            const uint8_t* ab = g_q8 + (size_t)bm * 128 * 256;
            #pragma unroll
            for (int i = 0; i < 8; i++) {
                int idx = i*256 + tid;
                int ch = idx >> 10, rem = idx & 1023;
                int row = rem >> 3, c16 = (rem & 7) * 16;
                cp16(su + ch*16384 + SW128(row*128 + c16),
                     ab + (size_t)row*256 + ch*128 + c16);
            }
        }

        if (seg < 16) {
            const uint8_t* Bcol = g_s8 + (size_t)(seg*4) * 128 * 256;
            #pragma unroll
            for (int g = 0; g < 4; g++) {
                fill_stage(su, Bcol + (g >> 1)*32768 + (g & 1)*128, g, tid);
                CP_COMMIT();
            }

            #pragma unroll
            for (int ct = 0; ct < 4; ct++) {
                #pragma unroll
                for (int mt = 0; mt < 2; mt++)
                    #pragma unroll
                    for (int nt = 0; nt < 8; nt++) {
                        acc[mt][nt][0] = 0u; acc[mt][nt][1] = 0u;
                    }

                if (ct < 3) CP_WAIT(2); else CP_WAIT(0);
                __syncthreads();
                mma_chunk(acc, su,         su + 32768 + ((2*ct)     & 3)*16384, laneA, laneB);
                mma_chunk(acc, su + 16384, su + 32768 + ((2*ct + 1) & 3)*16384, laneA, laneB);

                // ---- epilogue for col-block bn ----
                const int bn = seg*4 + ct;
                const bool diag = (bn == bm) && ((wm >> 1) == wn);
                const int sect = bm*2 + wn;
                const int lr = (wm & 1)*32 + (lane >> 2);
                float rsum[2][2] = {{0.f,0.f},{0.f,0.f}};

                #pragma unroll
                for (int mt = 0; mt < 2; mt++) {
                    #pragma unroll
                    for (int nt = 0; nt < 8; nt++) {
                        float2 f01 = __half22float2(*reinterpret_cast<__half2*>(&acc[mt][nt][0]));
                        float2 f23 = __half22float2(*reinterpret_cast<__half2*>(&acc[mt][nt][1]));
                        float e0 = __expf(f01.x * INV_TEMP);
                        float e1 = __expf(f01.y * INV_TEMP);
                        float e2 = __expf(f23.x * INV_TEMP);
                        float e3 = __expf(f23.y * INV_TEMP);
                        rsum[mt][0] += e0 + e1;
                        rsum[mt][1] += e2 + e3;
                        if (diag) {
                            int lcol = nt*8 + (lane & 3)*2;
                            float2* p0 = (float2*)(g_pos + (size_t)sect*4096 + (lr + mt*16)*64 + lcol);
                            float2* p1 = (float2*)(g_pos + (size_t)sect*4096 + (lr + mt*16 + 8)*64 + lcol);
                            *p0 = make_float2(e0, e1);
                            *p1 = make_float2(e2, e3);
                        }
                    }
                }
                #pragma unroll
                for (int mt = 0; mt < 2; mt++) {
                    #pragma unroll
                    for (int rr = 0; rr < 2; rr++) {
                        float v = rsum[mt][rr];
                        v += __shfl_xor_sync(0xffffffffu, v, 1);
                        v += __shfl_xor_sync(0xffffffffu, v, 2);
                        if ((lane & 3) == 0)
                            fs[wn*128 + wm*32 + mt*16 + rr*8 + (lane >> 2)] = v;
                    }
                }
                __syncthreads();
                if (tid < 128)
                    g_Epart[(size_t)bn*NROW + bm*128 + tid] = fs[tid] + fs[128 + tid];
                __syncthreads();

                if (ct < 2) {
                    const uint8_t* nb = Bcol + (size_t)(ct + 2)*32768;
                    fill_stage(su, nb,       (2*ct)     & 3, tid); CP_COMMIT();
                    fill_stage(su, nb + 128, (2*ct + 1) & 3, tid); CP_COMMIT();
                }
            }
        } else {
            // ---- title chunk: one 128-col block of section titles ----
            fill_stage(su, g_st8 +   0, 0, tid); CP_COMMIT();
            fill_stage(su, g_st8 + 128, 1, tid); CP_COMMIT();
            #pragma unroll
            for (int mt = 0; mt < 2; mt++)
                #pragma unroll
                for (int nt = 0; nt < 8; nt++) {
                    acc[mt][nt][0] = 0u; acc[mt][nt][1] = 0u;
                }

            CP_WAIT(0);
            __syncthreads();
            mma_chunk(acc, su,         su + 32768,         laneA, laneB);
            mma_chunk(acc, su + 16384, su + 32768 + 16384, laneA, laneB);

            #pragma unroll
            for (int nt = 0; nt < 8; nt++) {
                float2 a01 = __half22float2(*reinterpret_cast<__half2*>(&acc[0][nt][0]));
                float2 a23 = __half22float2(*reinterpret_cast<__half2*>(&acc[0][nt][1]));
                float2 b01 = __half22float2(*reinterpret_cast<__half2*>(&acc[1][nt][0]));
                float2 b23 = __half22float2(*reinterpret_cast<__half2*>(&acc[1][nt][1]));
                #pragma unroll
                for (int c01 = 0; c01 < 2; c01++) {
                    float v = (c01 == 0)
                        ? __expf(a01.x * INV_TEMP) + __expf(a23.x * INV_TEMP)
                          + __expf(b01.x * INV_TEMP) + __expf(b23.x * INV_TEMP)
                        : __expf(a01.y * INV_TEMP) + __expf(a23.y * INV_TEMP)
                          + __expf(b01.y * INV_TEMP) + __expf(b23.y * INV_TEMP);
                    v += __shfl_xor_sync(0xffffffffu, v, 4);
                    v += __shfl_xor_sync(0xffffffffu, v, 8);
                    v += __shfl_xor_sync(0xffffffffu, v, 16);
                    if (lane < 4)
                        fs[wm*128 + wn*64 + nt*8 + (lane & 3)*2 + c01] = v;
                }
            }
            __syncthreads();
            if (tid < 128)
                g_den_part[bm*SS + tid] = fs[tid] + fs[128 + tid] + fs[256 + tid] + fs[384 + tid];
            if (tid < 2) {
                int s0 = 2*bm + tid;
                g_num_part[s0] = fs[2*tid*128 + s0] + fs[(2*tid + 1)*128 + s0];
            }
            __syncthreads();
        }
    }

    // ================= grid barrier (all 296 CTAs co-resident) ===========
    CP_WAIT(0);
    __threadfence();
    __syncthreads();
    if (tid == 0) {
        unsigned gen = *(volatile unsigned*)&g_bgen;
        if (atomicAdd(&g_bcnt, 1u) == GRIDN - 1) {
            *(volatile unsigned*)&g_bcnt = 0u;     // self-reset for next launch
            __threadfence();
            atomicAdd(&g_bgen, 1u);                // release (monotonic)
        } else {
            while (*(volatile unsigned*)&g_bgen == gen) { }
        }
    }
    __syncthreads();
    __threadfence();

    // ================= phase 2: per-section loss (CTAs 0..127) ===========
    if (blockIdx.x < SS) {
        const int s = blockIdx.x;
        float* own     = fs;            // 64
        float* Es      = fs + 64;       // 64
        float* partial = fs + 128;      // 256
        float* epart   = fs + 384;      // 256
        float* dsh     = fs + 640;      // 64
        __shared__ bool is_last;
        const float* pos = g_pos + (size_t)s*4096;

        if (tid < 64) dsh[tid] = g_den_part[tid*SS + s];

        int q = tid >> 2, t4 = tid & 3;
        float p4 = 0.f;
        #pragma unroll
        for (int pp = 0; pp < 16; pp++) p4 += pos[q*64 + t4*16 + pp];
        partial[tid] = p4;

        float ep = 0.f;
        int er = tid >> 2, el = tid & 3;
        #pragma unroll
        for (int p = 0; p < 16; p++)
            ep += g_Epart[(size_t)(el*16 + p)*NROW + s*64 + er];
        epart[tid] = ep;
        __syncthreads();
        if (tid < 64) {
            own[tid] = partial[tid*4] + partial[tid*4+1] + partial[tid*4+2] + partial[tid*4+3];
            Es[tid]  = epart[tid*4] + epart[tid*4+1] + epart[tid*4+2] + epart[tid*4+3];
        }
        __syncthreads();

        const float term2 = __expf(-INV_TEMP) * (float)(NE - 1);
        float lsum = 0.f;
        #pragma unroll
        for (int it = 0; it < 16; it++) {
            int idx = it*256 + tid;
            int qq = idx >> 6;
            float pv = pos[idx];
            float neg = Es[qq] - own[qq];
            float t1 = fmaf(-LAM, pv, neg * (1.0f/(1.0f - LAM)));
            float Ng = fmaxf(fmaxf(t1, term2), 1e-8f);
            lsum += logf((pv + Ng) / pv);
        }
        partial[tid] = lsum;
        __syncthreads();
        for (int o = 128; o > 0; o >>= 1) {
            if (tid < o) partial[tid] += partial[tid + o];
            __syncthreads();
        }

        if (tid < 32) {
            float d = dsh[tid] + dsh[tid + 32];
            #pragma unroll
            for (int o = 16; o > 0; o >>= 1) d += __shfl_xor_sync(0xffffffffu, d, o);
            if (tid == 0) {
                g_final_part[s] = partial[0] + logf(d / g_num_part[s]);
                __threadfence();
                unsigned t = atomicAdd(&g_ticket, 1u);
                is_last = (t == SS - 1);
            }
        }
        __syncthreads();

        if (is_last) {
            __threadfence();
            float v = (tid < SS) ? *((volatile float*)&g_final_part[tid]) : 0.f;
            partial[tid] = v;
            __syncthreads();
            for (int o = 128; o > 0; o >>= 1) {
                if (tid < o) partial[tid] += partial[tid + o];
                __syncthreads();
            }
            if (tid == 0) out[0] = partial[0];
        }
    }
}

// ================= launch =================
extern "C" void kernel_launch(void* const* d_in, const int* in_sizes, int n_in,
                              void* d_out, int out_size) {
    (void)in_sizes; (void)n_in; (void)out_size;
    const float* sec  = (const float*)d_in[1];
    const float* ques = (const float*)d_in[2];
    const float* sent = (const float*)d_in[3];

    cudaFuncSetAttribute(gemm_kernel, cudaFuncAttributeMaxDynamicSharedMemorySize, SMEM_GEMM);

    norm_kernel<<<2064, 256>>>(ques, sent, sec);
    gemm_kernel<<<GRIDN, 256, SMEM_GEMM>>>((float*)d_out);
}

// round 16
// speedup vs baseline: 1.1869x; 1.1869x over previous
#include <cuda_runtime.h>
#include <cuda_fp16.h>
#include <cstdint>
#include <math.h>

// Problem constants
#define SS 128
#define QQ 64
#define PP 64
#define DD 256
#define NROW (SS*QQ)
#define NE   (SS*PP)
#define INV_TEMP (1.0f/0.07f)
#define LAM 0.1f
// exp(x/T) = 2^(x * INV_TEMP * log2(e)); scale folded into Q-side quantization
#define SCALE_A 20.6099318f

// -------- scratch (device globals) --------
__device__ uint8_t g_q8[NROW*DD];     // normalized questions x SCALE_A, row-major e4m3
__device__ uint8_t g_s8[NE*DD];       // normalized sentences,  row-major e4m3
__device__ uint8_t g_st8[SS*DD];      // normalized section titles, row-major e4m3
__device__ float g_pos[SS*QQ*PP];
__device__ float g_Epart[64*NROW];    // [bn][row], each slot written once
__device__ float g_den_part[64*SS];   // [bm][s]
__device__ float g_num_part[SS];
__device__ float g_final_part[SS];
__device__ unsigned g_ticket;

// ================= helpers =================
__device__ __forceinline__ uint32_t smem_u32(const void* p) {
    uint32_t a;
    asm("{ .reg .u64 t; cvta.to.shared.u64 t, %1; cvt.u32.u64 %0, t; }" : "=r"(a) : "l"(p));
    return a;
}
#define SW128(o) ((o) ^ (((o) >> 3) & 0x70))

__device__ __forceinline__ void cp16(uint32_t dst, const void* src) {
    asm volatile("cp.async.cg.shared.global [%0], [%1], 16;" :: "r"(dst), "l"(src) : "memory");
}
#define CP_COMMIT() asm volatile("cp.async.commit_group;" ::: "memory")
#define CP_WAIT(n)  asm volatile("cp.async.wait_group %0;" :: "n"(n) : "memory")

__device__ __forceinline__ void ldsm4(uint32_t* r, uint32_t addr) {
    asm volatile("ldmatrix.sync.aligned.m8n8.x4.shared.b16 {%0,%1,%2,%3}, [%4];"
        : "=r"(r[0]), "=r"(r[1]), "=r"(r[2]), "=r"(r[3]) : "r"(addr));
}
// fp8 e4m3 x e4m3 -> f16 accumulator (2 b32 regs = 4 halves)
__device__ __forceinline__ void mma16832h(uint32_t* c, const uint32_t* a, const uint32_t* b) {
    asm volatile(
        "mma.sync.aligned.m16n8k32.row.col.f16.e4m3.e4m3.f16 "
        "{%0,%1}, {%2,%3,%4,%5}, {%6,%7}, {%0,%1};"
        : "+r"(c[0]), "+r"(c[1])
        : "r"(a[0]), "r"(a[1]), "r"(a[2]), "r"(a[3]), "r"(b[0]), "r"(b[1]));
}
__device__ __forceinline__ uint16_t f2e4m3x2(float hi, float lo) {
    uint16_t r;
    asm("cvt.rn.satfinite.e4m3x2.f32 %0, %1, %2;" : "=h"(r) : "f"(hi), "f"(lo));
    return r;
}
// half2 2^x on a raw f16x2 register; returns f16x2 register
__device__ __forceinline__ uint32_t ex2_f16x2(uint32_t x) {
    uint32_t r;
    asm("ex2.approx.f16x2 %0, %1;" : "=r"(r) : "r"(x));
    return r;
}
__device__ __forceinline__ float2 h2f2(uint32_t h) {
    return __half22float2(*reinterpret_cast<__half2*>(&h));
}

// ================= normalize -> fp8 (one warp per row; proven) =========
__global__ void __launch_bounds__(256) norm_kernel(const float* __restrict__ q_in,
                                                   const float* __restrict__ s_in,
                                                   const float* __restrict__ st_in) {
    if (blockIdx.x == 0 && threadIdx.x == 0) g_ticket = 0;   // reset per launch
    int warp = threadIdx.x >> 5, lane = threadIdx.x & 31;
    int row = blockIdx.x * 8 + warp;        // 2064 blocks * 8 rows = 16512 rows
    const float* src; uint8_t* dst; int col;
    float extra = 1.0f;
    if (row < NROW)        { col = row;          src = q_in  + (size_t)col * DD; dst = g_q8;
                             extra = SCALE_A; }  // fold exp scale into Q side
    else if (row < 2*NROW) { col = row - NROW;   src = s_in  + (size_t)col * DD; dst = g_s8;  }
    else                   { col = row - 2*NROW; src = st_in + (size_t)col * DD; dst = g_st8; }

    float4 v0 = ((const float4*)src)[lane*2];
    float4 v1 = ((const float4*)src)[lane*2 + 1];
    float ss = v0.x*v0.x + v0.y*v0.y + v0.z*v0.z + v0.w*v0.w
             + v1.x*v1.x + v1.y*v1.y + v1.z*v1.z + v1.w*v1.w;
    #pragma unroll
    for (int o = 16; o > 0; o >>= 1) ss += __shfl_xor_sync(0xffffffffu, ss, o);
    float sc = extra / fmaxf(sqrtf(ss), 1e-12f);
    uint32_t lo = (uint32_t)f2e4m3x2(v0.y*sc, v0.x*sc)
                | ((uint32_t)f2e4m3x2(v0.w*sc, v0.z*sc) << 16);
    uint32_t hi = (uint32_t)f2e4m3x2(v1.y*sc, v1.x*sc)
                | ((uint32_t)f2e4m3x2(v1.w*sc, v1.z*sc) << 16);
    *(uint2*)(dst + (size_t)col*DD + lane*8) = make_uint2(lo, hi);
}

// ================= fused qs+sq GEMM via FP8 MMA (f16 acc, ex2 epilogue) ====
// grid (64, 17): bm = 128-row block; seg<16 -> four 128-col sentence blocks;
// seg==16 -> title block.
// smem: A 2x16KB @0; B 4x16KB @32768; float scratch @98304. total 100352.
#define SMEM_GEMM 100352

__device__ __forceinline__ void fill_stage(uint32_t su, const uint8_t* bbase,
                                           int stagebuf, int tid) {
    uint32_t d = su + 32768 + stagebuf * 16384;
    #pragma unroll
    for (int i = 0; i < 4; i++) {
        int idx = i*256 + tid;
        int row = idx >> 3, c16 = (idx & 7) * 16;
        cp16(d + SW128(row*128 + c16), bbase + (size_t)row*256 + c16);
    }
}

// Pipelined MMA over one (128x128 tile) x (K=128 chunk): fragment double-buffer.
// laneA/laneB pre-swizzled; addr(kk) = base ^ (kk*32) [+ mt/np*2048].
__device__ __forceinline__ void mma_chunk(uint32_t (&acc)[2][8][2], uint32_t as, uint32_t bs,
                                          uint32_t laneA, uint32_t laneB) {
    uint32_t a[2][2][4], b[2][4][4];
    {
        const uint32_t a0 = as + laneA, b0 = bs + laneB;
        ldsm4(a[0][0], a0);
        ldsm4(a[0][1], a0 + 2048);
        #pragma unroll
        for (int np = 0; np < 4; np++) ldsm4(b[0][np], b0 + np*2048);
    }
    #pragma unroll
    for (int kk = 0; kk < 4; kk++) {
        const int cur = kk & 1, nxt = cur ^ 1;
        if (kk < 3) {
            const uint32_t x = (uint32_t)(kk + 1) * 32u;
            const uint32_t a0 = as + (laneA ^ x), b0 = bs + (laneB ^ x);
            ldsm4(a[nxt][0], a0);
            ldsm4(a[nxt][1], a0 + 2048);
            #pragma unroll
            for (int np = 0; np < 4; np++) ldsm4(b[nxt][np], b0 + np*2048);
        }
        #pragma unroll
        for (int mt = 0; mt < 2; mt++)
            #pragma unroll
            for (int nt = 0; nt < 8; nt++)
                mma16832h(acc[mt][nt], a[cur][mt], b[cur][nt >> 1] + (nt & 1)*2);
    }
}

__global__ void __launch_bounds__(256, 2) gemm_kernel() {
    extern __shared__ char smem[];
    const uint32_t su = smem_u32(smem);
    float* fs = (float*)(smem + 98304);
    const int tid = threadIdx.x;
    const int lane = tid & 31, wid = tid >> 5;
    const int wm = wid >> 1, wn = wid & 1;
    const int bm = blockIdx.x, seg = blockIdx.y;

    // pre-swizzled lane bases (XOR trick: kk*32 toggles bits 5-6 w/o carry)
    const int arow = wm*32 + (lane & 15);
    const int aoff = (lane >> 4) * 16;
    const uint32_t laneA = (uint32_t)(arow*128) + (uint32_t)(aoff ^ ((arow & 7) << 4));
    const int brow = wn*64 + (lane & 7) + ((lane >> 4) & 1) * 8;
    const int boff = ((lane >> 3) & 1) * 16;
    const uint32_t laneB = (uint32_t)(brow*128) + (uint32_t)(boff ^ ((brow & 7) << 4));

    // ---- A load: 32KB (2 K-chunks), folds into first commit group ----
    {
        const uint8_t* ab = g_q8 + (size_t)bm * 128 * 256;
        #pragma unroll
        for (int i = 0; i < 8; i++) {
            int idx = i*256 + tid;
            int ch = idx >> 10, rem = idx & 1023;
            int row = rem >> 3, c16 = (rem & 7) * 16;
            cp16(su + ch*16384 + SW128(row*128 + c16),
                 ab + (size_t)row*256 + ch*128 + c16);
        }
    }

    uint32_t acc[2][8][2];

    if (seg < 16) {
        const uint8_t* Bcol = g_s8 + (size_t)(seg*4) * 128 * 256;
        // groups: G0 = A + st0, G1 = st1, G2 = st2, G3 = st3
        #pragma unroll
        for (int g = 0; g < 4; g++) {
            fill_stage(su, Bcol + (g >> 1)*32768 + (g & 1)*128, g, tid);
            CP_COMMIT();
        }

        #pragma unroll
        for (int ct = 0; ct < 4; ct++) {
            #pragma unroll
            for (int mt = 0; mt < 2; mt++)
                #pragma unroll
                for (int nt = 0; nt < 8; nt++) {
                    acc[mt][nt][0] = 0u; acc[mt][nt][1] = 0u;
                }

            // both K-chunk stages of this col-tile are >= 2 groups old
            if (ct < 3) CP_WAIT(2); else CP_WAIT(0);
            __syncthreads();
            mma_chunk(acc, su,         su + 32768 + ((2*ct)     & 3)*16384, laneA, laneB);
            mma_chunk(acc, su + 16384, su + 32768 + ((2*ct + 1) & 3)*16384, laneA, laneB);

            // ---- epilogue: exp via ex2.f16x2 on raw acc, diag pos, partials ----
            const int bn = seg*4 + ct;
            const bool diag = (bn == bm) && ((wm >> 1) == wn);
            const int sect = bm*2 + wn;
            const int lr = (wm & 1)*32 + (lane >> 2);
            float rsum[2][2] = {{0.f,0.f},{0.f,0.f}};

            #pragma unroll
            for (int mt = 0; mt < 2; mt++) {
                #pragma unroll
                for (int nt = 0; nt < 8; nt++) {
                    float2 f01 = h2f2(ex2_f16x2(acc[mt][nt][0]));
                    float2 f23 = h2f2(ex2_f16x2(acc[mt][nt][1]));
                    rsum[mt][0] += f01.x + f01.y;
                    rsum[mt][1] += f23.x + f23.y;
                    if (diag) {
                        int lcol = nt*8 + (lane & 3)*2;
                        float2* p0 = (float2*)(g_pos + (size_t)sect*4096 + (lr + mt*16)*64 + lcol);
                        float2* p1 = (float2*)(g_pos + (size_t)sect*4096 + (lr + mt*16 + 8)*64 + lcol);
                        *p0 = f01;
                        *p1 = f23;
                    }
                }
            }
            #pragma unroll
            for (int mt = 0; mt < 2; mt++) {
                #pragma unroll
                for (int rr = 0; rr < 2; rr++) {
                    float v = rsum[mt][rr];
                    v += __shfl_xor_sync(0xffffffffu, v, 1);
                    v += __shfl_xor_sync(0xffffffffu, v, 2);
                    if ((lane & 3) == 0)
                        fs[wn*128 + wm*32 + mt*16 + rr*8 + (lane >> 2)] = v;
                }
            }
            __syncthreads();
            if (tid < 128)
                g_Epart[(size_t)bn*NROW + bm*128 + tid] = fs[tid] + fs[128 + tid];
            __syncthreads();

            // refill the two consumed stages for col-tile ct+2
            if (ct < 2) {
                const uint8_t* nb = Bcol + (size_t)(ct + 2)*32768;
                fill_stage(su, nb,       (2*ct)     & 3, tid); CP_COMMIT();
                fill_stage(su, nb + 128, (2*ct + 1) & 3, tid); CP_COMMIT();
            }
        }
    } else {
        // ---- title path: one 128-col block of section titles ----
        fill_stage(su, g_st8 +   0, 0, tid); CP_COMMIT();
        fill_stage(su, g_st8 + 128, 1, tid); CP_COMMIT();
        #pragma unroll
        for (int mt = 0; mt < 2; mt++)
            #pragma unroll
            for (int nt = 0; nt < 8; nt++) {
                acc[mt][nt][0] = 0u; acc[mt][nt][1] = 0u;
            }

        CP_WAIT(0);
        __syncthreads();
        mma_chunk(acc, su,         su + 32768,         laneA, laneB);
        mma_chunk(acc, su + 16384, su + 32768 + 16384, laneA, laneB);

        // column sums -> den_part / num_part
        #pragma unroll
        for (int nt = 0; nt < 8; nt++) {
            float2 a01 = h2f2(ex2_f16x2(acc[0][nt][0]));
            float2 a23 = h2f2(ex2_f16x2(acc[0][nt][1]));
            float2 b01 = h2f2(ex2_f16x2(acc[1][nt][0]));
            float2 b23 = h2f2(ex2_f16x2(acc[1][nt][1]));
            #pragma unroll
            for (int c01 = 0; c01 < 2; c01++) {
                float v = (c01 == 0) ? (a01.x + a23.x + b01.x + b23.x)
                                     : (a01.y + a23.y + b01.y + b23.y);
                v += __shfl_xor_sync(0xffffffffu, v, 4);
                v += __shfl_xor_sync(0xffffffffu, v, 8);
                v += __shfl_xor_sync(0xffffffffu, v, 16);
                if (lane < 4)
                    fs[wm*128 + wn*64 + nt*8 + (lane & 3)*2 + c01] = v;
            }
        }
        __syncthreads();
        if (tid < 128)
            g_den_part[bm*SS + tid] = fs[tid] + fs[128 + tid] + fs[256 + tid] + fs[384 + tid];
        if (tid < 2) {
            int s0 = 2*bm + tid;
            g_num_part[s0] = fs[2*tid*128 + s0] + fs[(2*tid + 1)*128 + s0];
        }
    }
}

// ================= qs loss assembly + sq term + fused final reduce =================
__global__ void __launch_bounds__(256) qs_loss_kernel(float* out) {
    int s = blockIdx.x, tid = threadIdx.x;   // 256 threads
    __shared__ float own[64], Es[64], partial[256], epart[256], dsh[64];
    __shared__ bool is_last;
    const float* pos = g_pos + (size_t)s*4096;

    if (tid < 64) dsh[tid] = g_den_part[tid*SS + s];

    int q = tid >> 2, t4 = tid & 3;
    float p4 = 0.f;
    #pragma unroll
    for (int pp = 0; pp < 16; pp++) p4 += pos[q*64 + t4*16 + pp];
    partial[tid] = p4;

    float ep = 0.f;
    int er = tid >> 2, el = tid & 3;
    #pragma unroll
    for (int p = 0; p < 16; p++)
        ep += g_Epart[(size_t)(el*16 + p)*NROW + s*64 + er];
    epart[tid] = ep;
    __syncthreads();
    if (tid < 64) {
        own[tid] = partial[tid*4] + partial[tid*4+1] + partial[tid*4+2] + partial[tid*4+3];
        Es[tid]  = epart[tid*4] + epart[tid*4+1] + epart[tid*4+2] + epart[tid*4+3];
    }
    __syncthreads();

    const float term2 = __expf(-INV_TEMP) * (float)(NE - 1);
    float lsum = 0.f;
    #pragma unroll
    for (int it = 0; it < 16; it++) {
        int idx = it*256 + tid;
        int qq = idx >> 6;
        float pv = pos[idx];
        float neg = Es[qq] - own[qq];
        float t1 = fmaf(-LAM, pv, neg * (1.0f/(1.0f - LAM)));
        float Ng = fmaxf(fmaxf(t1, term2), 1e-8f);
        lsum += logf((pv + Ng) / pv);
    }
    partial[tid] = lsum;
    __syncthreads();
    for (int o = 128; o > 0; o >>= 1) {
        if (tid < o) partial[tid] += partial[tid + o];
        __syncthreads();
    }

    // section total: qs part + sq part
    if (tid < 32) {
        float d = dsh[tid] + dsh[tid + 32];
        #pragma unroll
        for (int o = 16; o > 0; o >>= 1) d += __shfl_xor_sync(0xffffffffu, d, o);
        if (tid == 0) {
            g_final_part[s] = partial[0] + logf(d / g_num_part[s]);
            __threadfence();
            unsigned t = atomicAdd(&g_ticket, 1u);
            is_last = (t == SS - 1);
        }
    }
    __syncthreads();

    if (is_last) {
        __threadfence();
        float v = (tid < SS) ? *((volatile float*)&g_final_part[tid]) : 0.f;
        partial[tid] = v;
        __syncthreads();
        for (int o = 128; o > 0; o >>= 1) {
            if (tid < o) partial[tid] += partial[tid + o];
            __syncthreads();
        }
        if (tid == 0) out[0] = partial[0];
    }
}

// ================= launch =================
extern "C" void kernel_launch(void* const* d_in, const int* in_sizes, int n_in,
                              void* d_out, int out_size) {
    (void)in_sizes; (void)n_in; (void)out_size;
    const float* sec  = (const float*)d_in[1];
    const float* ques = (const float*)d_in[2];
    const float* sent = (const float*)d_in[3];

    cudaFuncSetAttribute(gemm_kernel, cudaFuncAttributeMaxDynamicSharedMemorySize, SMEM_GEMM);

    norm_kernel<<<2064, 256>>>(ques, sent, sec);
    dim3 g(64, 17);
    gemm_kernel<<<g, 256, SMEM_GEMM>>>();
    qs_loss_kernel<<<SS, 256>>>((float*)d_out);
}

// round 17
// speedup vs baseline: 1.1899x; 1.0025x over previous
#include <cuda_runtime.h>
#include <cuda_fp16.h>
#include <cstdint>
#include <math.h>

// Problem constants
#define SS 128
#define QQ 64
#define PP 64
#define DD 256
#define NROW (SS*QQ)
#define NE   (SS*PP)
#define INV_TEMP (1.0f/0.07f)
#define LAM 0.1f
// exp(x/T) = 2^(x * INV_TEMP * log2(e)); scale folded into Q-side quantization
#define SCALE_A 20.6099318f

// -------- scratch (device globals) --------
__device__ uint8_t g_q8[NROW*DD];     // normalized questions x SCALE_A, row-major e4m3
__device__ uint8_t g_s8[NE*DD];       // normalized sentences,  row-major e4m3
__device__ uint8_t g_st8[SS*DD];      // normalized section titles, row-major e4m3
__device__ float g_pos[SS*QQ*PP];
__device__ float g_Epart[64*NROW];    // [bn][row], each slot written once
__device__ float g_den_part[64*SS];   // [bm][s]
__device__ float g_num_part[SS];
__device__ float g_final_part[SS];
__device__ unsigned g_ticket;

// ================= helpers =================
__device__ __forceinline__ uint32_t smem_u32(const void* p) {
    uint32_t a;
    asm("{ .reg .u64 t; cvta.to.shared.u64 t, %1; cvt.u32.u64 %0, t; }" : "=r"(a) : "l"(p));
    return a;
}
#define SW128(o) ((o) ^ (((o) >> 3) & 0x70))

__device__ __forceinline__ void cp16(uint32_t dst, const void* src) {
    asm volatile("cp.async.cg.shared.global [%0], [%1], 16;" :: "r"(dst), "l"(src) : "memory");
}
#define CP_COMMIT() asm volatile("cp.async.commit_group;" ::: "memory")
#define CP_WAIT(n)  asm volatile("cp.async.wait_group %0;" :: "n"(n) : "memory")

__device__ __forceinline__ void ldsm4(uint32_t* r, uint32_t addr) {
    asm volatile("ldmatrix.sync.aligned.m8n8.x4.shared.b16 {%0,%1,%2,%3}, [%4];"
        : "=r"(r[0]), "=r"(r[1]), "=r"(r[2]), "=r"(r[3]) : "r"(addr));
}
// fp8 e4m3 x e4m3 -> f16 accumulator (2 b32 regs = 4 halves)
__device__ __forceinline__ void mma16832h(uint32_t* c, const uint32_t* a, const uint32_t* b) {
    asm volatile(
        "mma.sync.aligned.m16n8k32.row.col.f16.e4m3.e4m3.f16 "
        "{%0,%1}, {%2,%3,%4,%5}, {%6,%7}, {%0,%1};"
        : "+r"(c[0]), "+r"(c[1])
        : "r"(a[0]), "r"(a[1]), "r"(a[2]), "r"(a[3]), "r"(b[0]), "r"(b[1]));
}
__device__ __forceinline__ uint16_t f2e4m3x2(float hi, float lo) {
    uint16_t r;
    asm("cvt.rn.satfinite.e4m3x2.f32 %0, %1, %2;" : "=h"(r) : "f"(hi), "f"(lo));
    return r;
}
// half2 2^x on a raw f16x2 register; returns f16x2 register
__device__ __forceinline__ uint32_t ex2_f16x2(uint32_t x) {
    uint32_t r;
    asm("ex2.approx.f16x2 %0, %1;" : "=r"(r) : "r"(x));
    return r;
}
__device__ __forceinline__ uint32_t hadd2(uint32_t a, uint32_t b) {
    uint32_t r;
    asm("add.rn.f16x2 %0, %1, %2;" : "=r"(r) : "r"(a), "r"(b));
    return r;
}
__device__ __forceinline__ float2 h2f2(uint32_t h) {
    return __half22float2(*reinterpret_cast<__half2*>(&h));
}

// ================= normalize -> fp8 (one warp per row; proven) =========
__global__ void __launch_bounds__(256) norm_kernel(const float* __restrict__ q_in,
                                                   const float* __restrict__ s_in,
                                                   const float* __restrict__ st_in) {
    if (blockIdx.x == 0 && threadIdx.x == 0) g_ticket = 0;   // reset per launch
    int warp = threadIdx.x >> 5, lane = threadIdx.x & 31;
    int row = blockIdx.x * 8 + warp;        // 2064 blocks * 8 rows = 16512 rows
    const float* src; uint8_t* dst; int col;
    float extra = 1.0f;
    if (row < NROW)        { col = row;          src = q_in  + (size_t)col * DD; dst = g_q8;
                             extra = SCALE_A; }  // fold exp scale into Q side
    else if (row < 2*NROW) { col = row - NROW;   src = s_in  + (size_t)col * DD; dst = g_s8;  }
    else                   { col = row - 2*NROW; src = st_in + (size_t)col * DD; dst = g_st8; }

    float4 v0 = ((const float4*)src)[lane*2];
    float4 v1 = ((const float4*)src)[lane*2 + 1];
    float ss = v0.x*v0.x + v0.y*v0.y + v0.z*v0.z + v0.w*v0.w
             + v1.x*v1.x + v1.y*v1.y + v1.z*v1.z + v1.w*v1.w;
    #pragma unroll
    for (int o = 16; o > 0; o >>= 1) ss += __shfl_xor_sync(0xffffffffu, ss, o);
    float sc = extra / fmaxf(sqrtf(ss), 1e-12f);
    uint32_t lo = (uint32_t)f2e4m3x2(v0.y*sc, v0.x*sc)
                | ((uint32_t)f2e4m3x2(v0.w*sc, v0.z*sc) << 16);
    uint32_t hi = (uint32_t)f2e4m3x2(v1.y*sc, v1.x*sc)
                | ((uint32_t)f2e4m3x2(v1.w*sc, v1.z*sc) << 16);
    *(uint2*)(dst + (size_t)col*DD + lane*8) = make_uint2(lo, hi);
}

// ================= fused qs+sq GEMM via FP8 MMA (f16 acc, ex2+hadd2) ======
// grid (64, 17): bm = 128-row block; seg<16 -> four 128-col sentence blocks;
// seg==16 -> title block.
// smem: A 2x16KB @0; B 4x16KB @32768; float scratch @98304. total 100352.
#define SMEM_GEMM 100352

__device__ __forceinline__ void fill_stage(uint32_t su, const uint8_t* bbase,
                                           int stagebuf, int tid) {
    uint32_t d = su + 32768 + stagebuf * 16384;
    #pragma unroll
    for (int i = 0; i < 4; i++) {
        int idx = i*256 + tid;
        int row = idx >> 3, c16 = (idx & 7) * 16;
        cp16(d + SW128(row*128 + c16), bbase + (size_t)row*256 + c16);
    }
}

// Pipelined MMA over one (128x128 tile) x (K=128 chunk): fragment double-buffer.
// laneA/laneB pre-swizzled; addr(kk) = base ^ (kk*32) [+ mt/np*2048].
__device__ __forceinline__ void mma_chunk(uint32_t (&acc)[2][8][2], uint32_t as, uint32_t bs,
                                          uint32_t laneA, uint32_t laneB) {
    uint32_t a[2][2][4], b[2][4][4];
    {
        const uint32_t a0 = as + laneA, b0 = bs + laneB;
        ldsm4(a[0][0], a0);
        ldsm4(a[0][1], a0 + 2048);
        #pragma unroll
        for (int np = 0; np < 4; np++) ldsm4(b[0][np], b0 + np*2048);
    }
    #pragma unroll
    for (int kk = 0; kk < 4; kk++) {
        const int cur = kk & 1, nxt = cur ^ 1;
        if (kk < 3) {
            const uint32_t x = (uint32_t)(kk + 1) * 32u;
            const uint32_t a0 = as + (laneA ^ x), b0 = bs + (laneB ^ x);
            ldsm4(a[nxt][0], a0);
            ldsm4(a[nxt][1], a0 + 2048);
            #pragma unroll
            for (int np = 0; np < 4; np++) ldsm4(b[nxt][np], b0 + np*2048);
        }
        #pragma unroll
        for (int mt = 0; mt < 2; mt++)
            #pragma unroll
            for (int nt = 0; nt < 8; nt++)
                mma16832h(acc[mt][nt], a[cur][mt], b[cur][nt >> 1] + (nt & 1)*2);
    }
}

__global__ void __launch_bounds__(256, 2) gemm_kernel() {
    extern __shared__ char smem[];
    const uint32_t su = smem_u32(smem);
    float* fs = (float*)(smem + 98304);
    const int tid = threadIdx.x;
    const int lane = tid & 31, wid = tid >> 5;
    const int wm = wid >> 1, wn = wid & 1;
    const int bm = blockIdx.x, seg = blockIdx.y;

    // pre-swizzled lane bases (XOR trick: kk*32 toggles bits 5-6 w/o carry)
    const int arow = wm*32 + (lane & 15);
    const int aoff = (lane >> 4) * 16;
    const uint32_t laneA = (uint32_t)(arow*128) + (uint32_t)(aoff ^ ((arow & 7) << 4));
    const int brow = wn*64 + (lane & 7) + ((lane >> 4) & 1) * 8;
    const int boff = ((lane >> 3) & 1) * 16;
    const uint32_t laneB = (uint32_t)(brow*128) + (uint32_t)(boff ^ ((brow & 7) << 4));

    // ---- A load: 32KB (2 K-chunks), folds into first commit group ----
    {
        const uint8_t* ab = g_q8 + (size_t)bm * 128 * 256;
        #pragma unroll
        for (int i = 0; i < 8; i++) {
            int idx = i*256 + tid;
            int ch = idx >> 10, rem = idx & 1023;
            int row = rem >> 3, c16 = (rem & 7) * 16;
            cp16(su + ch*16384 + SW128(row*128 + c16),
                 ab + (size_t)row*256 + ch*128 + c16);
        }
    }

    uint32_t acc[2][8][2];

    if (seg < 16) {
        const uint8_t* Bcol = g_s8 + (size_t)(seg*4) * 128 * 256;
        // groups: G0 = A + st0, G1 = st1, G2 = st2, G3 = st3
        #pragma unroll
        for (int g = 0; g < 4; g++) {
            fill_stage(su, Bcol + (g >> 1)*32768 + (g & 1)*128, g, tid);
            CP_COMMIT();
        }

        #pragma unroll
        for (int ct = 0; ct < 4; ct++) {
            #pragma unroll
            for (int mt = 0; mt < 2; mt++)
                #pragma unroll
                for (int nt = 0; nt < 8; nt++) {
                    acc[mt][nt][0] = 0u; acc[mt][nt][1] = 0u;
                }

            // both K-chunk stages of this col-tile are >= 2 groups old
            if (ct < 3) CP_WAIT(2); else CP_WAIT(0);
            __syncthreads();
            mma_chunk(acc, su,         su + 32768 + ((2*ct)     & 3)*16384, laneA, laneB);
            mma_chunk(acc, su + 16384, su + 32768 + ((2*ct + 1) & 3)*16384, laneA, laneB);

            // ---- epilogue: ex2 + half2 row-sum accumulation ----
            const int bn = seg*4 + ct;
            const bool diag = (bn == bm) && ((wm >> 1) == wn);
            const int sect = bm*2 + wn;
            const int lr = (wm & 1)*32 + (lane >> 2);
            float rsum[2][2];

            #pragma unroll
            for (int mt = 0; mt < 2; mt++) {
                uint32_t h0 = 0u, h1 = 0u;   // f16x2 zeros
                #pragma unroll
                for (int nt = 0; nt < 8; nt++) {
                    uint32_t e0 = ex2_f16x2(acc[mt][nt][0]);
                    uint32_t e1 = ex2_f16x2(acc[mt][nt][1]);
                    h0 = hadd2(h0, e0);
                    h1 = hadd2(h1, e1);
                    if (diag) {
                        int lcol = nt*8 + (lane & 3)*2;
                        float2* p0 = (float2*)(g_pos + (size_t)sect*4096 + (lr + mt*16)*64 + lcol);
                        float2* p1 = (float2*)(g_pos + (size_t)sect*4096 + (lr + mt*16 + 8)*64 + lcol);
                        *p0 = h2f2(e0);
                        *p1 = h2f2(e1);
                    }
                }
                float2 f0 = h2f2(h0), f1 = h2f2(h1);
                rsum[mt][0] = f0.x + f0.y;
                rsum[mt][1] = f1.x + f1.y;
            }
            #pragma unroll
            for (int mt = 0; mt < 2; mt++) {
                #pragma unroll
                for (int rr = 0; rr < 2; rr++) {
                    float v = rsum[mt][rr];
                    v += __shfl_xor_sync(0xffffffffu, v, 1);
                    v += __shfl_xor_sync(0xffffffffu, v, 2);
                    if ((lane & 3) == 0)
                        fs[wn*128 + wm*32 + mt*16 + rr*8 + (lane >> 2)] = v;
                }
            }
            __syncthreads();
            if (tid < 128)
                g_Epart[(size_t)bn*NROW + bm*128 + tid] = fs[tid] + fs[128 + tid];
            __syncthreads();

            // refill the two consumed stages for col-tile ct+2
            if (ct < 2) {
                const uint8_t* nb = Bcol + (size_t)(ct + 2)*32768;
                fill_stage(su, nb,       (2*ct)     & 3, tid); CP_COMMIT();
                fill_stage(su, nb + 128, (2*ct + 1) & 3, tid); CP_COMMIT();
            }
        }
    } else {
        // ---- title path: one 128-col block of section titles ----
        fill_stage(su, g_st8 +   0, 0, tid); CP_COMMIT();
        fill_stage(su, g_st8 + 128, 1, tid); CP_COMMIT();
        #pragma unroll
        for (int mt = 0; mt < 2; mt++)
            #pragma unroll
            for (int nt = 0; nt < 8; nt++) {
                acc[mt][nt][0] = 0u; acc[mt][nt][1] = 0u;
            }

        CP_WAIT(0);
        __syncthreads();
        mma_chunk(acc, su,         su + 32768,         laneA, laneB);
        mma_chunk(acc, su + 16384, su + 32768 + 16384, laneA, laneB);

        // column sums via half2 (both halves = adjacent columns, 4 rows summed)
        #pragma unroll
        for (int nt = 0; nt < 8; nt++) {
            uint32_t h = hadd2(hadd2(ex2_f16x2(acc[0][nt][0]), ex2_f16x2(acc[0][nt][1])),
                               hadd2(ex2_f16x2(acc[1][nt][0]), ex2_f16x2(acc[1][nt][1])));
            float2 f = h2f2(h);
            #pragma unroll
            for (int c01 = 0; c01 < 2; c01++) {
                float v = (c01 == 0) ? f.x : f.y;
                v += __shfl_xor_sync(0xffffffffu, v, 4);
                v += __shfl_xor_sync(0xffffffffu, v, 8);
                v += __shfl_xor_sync(0xffffffffu, v, 16);
                if (lane < 4)
                    fs[wm*128 + wn*64 + nt*8 + (lane & 3)*2 + c01] = v;
            }
        }
        __syncthreads();
        if (tid < 128)
            g_den_part[bm*SS + tid] = fs[tid] + fs[128 + tid] + fs[256 + tid] + fs[384 + tid];
        if (tid < 2) {
            int s0 = 2*bm + tid;
            g_num_part[s0] = fs[2*tid*128 + s0] + fs[(2*tid + 1)*128 + s0];
        }
    }
}

// ================= qs loss assembly + sq term + fused final reduce =================
__global__ void __launch_bounds__(256) qs_loss_kernel(float* out) {
    int s = blockIdx.x, tid = threadIdx.x;   // 256 threads
    __shared__ float own[64], Es[64], partial[256], epart[256], dsh[64];
    __shared__ bool is_last;
    const float* pos = g_pos + (size_t)s*4096;

    if (tid < 64) dsh[tid] = g_den_part[tid*SS + s];

    int q = tid >> 2, t4 = tid & 3;
    float p4 = 0.f;
    #pragma unroll
    for (int pp = 0; pp < 16; pp++) p4 += pos[q*64 + t4*16 + pp];
    partial[tid] = p4;

    float ep = 0.f;
    int er = tid >> 2, el = tid & 3;
    #pragma unroll
    for (int p = 0; p < 16; p++)
        ep += g_Epart[(size_t)(el*16 + p)*NROW + s*64 + er];
    epart[tid] = ep;
    __syncthreads();
    if (tid < 64) {
        own[tid] = partial[tid*4] + partial[tid*4+1] + partial[tid*4+2] + partial[tid*4+3];
        Es[tid]  = epart[tid*4] + epart[tid*4+1] + epart[tid*4+2] + epart[tid*4+3];
    }
    __syncthreads();

    const float term2 = __expf(-INV_TEMP) * (float)(NE - 1);
    float lsum = 0.f;
    #pragma unroll
    for (int it = 0; it < 16; it++) {
        int idx = it*256 + tid;
        int qq = idx >> 6;
        float pv = pos[idx];
        float neg = Es[qq] - own[qq];
        float t1 = fmaf(-LAM, pv, neg * (1.0f/(1.0f - LAM)));
        float Ng = fmaxf(fmaxf(t1, term2), 1e-8f);
        lsum += logf((pv + Ng) / pv);
    }
    partial[tid] = lsum;
    __syncthreads();
    for (int o = 128; o > 0; o >>= 1) {
        if (tid < o) partial[tid] += partial[tid + o];
        __syncthreads();
    }

    // section total: qs part + sq part
    if (tid < 32) {
        float d = dsh[tid] + dsh[tid + 32];
        #pragma unroll
        for (int o = 16; o > 0; o >>= 1) d += __shfl_xor_sync(0xffffffffu, d, o);
        if (tid == 0) {
            g_final_part[s] = partial[0] + logf(d / g_num_part[s]);
            __threadfence();
            unsigned t = atomicAdd(&g_ticket, 1u);
            is_last = (t == SS - 1);
        }
    }
    __syncthreads();

    if (is_last) {
        __threadfence();
        float v = (tid < SS) ? *((volatile float*)&g_final_part[tid]) : 0.f;
        partial[tid] = v;
        __syncthreads();
        for (int o = 128; o > 0; o >>= 1) {
            if (tid < o) partial[tid] += partial[tid + o];
            __syncthreads();
        }
        if (tid == 0) out[0] = partial[0];
    }
}

// ================= launch =================
extern "C" void kernel_launch(void* const* d_in, const int* in_sizes, int n_in,
                              void* d_out, int out_size) {
    (void)in_sizes; (void)n_in; (void)out_size;
    const float* sec  = (const float*)d_in[1];
    const float* ques = (const float*)d_in[2];
    const float* sent = (const float*)d_in[3];

    cudaFuncSetAttribute(gemm_kernel, cudaFuncAttributeMaxDynamicSharedMemorySize, SMEM_GEMM);

    norm_kernel<<<2064, 256>>>(ques, sent, sec);
    dim3 g(64, 17);
    gemm_kernel<<<g, 256, SMEM_GEMM>>>();
    qs_loss_kernel<<<SS, 256>>>((float*)d_out);
}